// round 12
// baseline (speedup 1.0000x reference)
#include <cuda_runtime.h>
#include <cuda_fp16.h>
#include <mma.h>
#include <cstdint>

using namespace nvcuda;

#define MAXN 500000
#define MAXE 500000
#define F 128

// ---------------- scratch (static device globals; no allocation) ----------------
__device__ __half g_xacc[(size_t)MAXN * F]; // per-node accumulated x rows (fp16)
__device__ __half g_acc[(size_t)MAXN * F];  // relu(xacc@W + bias) (fp16)
__device__ float g_s[MAXN];                 // per-node dot with a_src
__device__ float g_d[MAXN];                 // per-node dot with a_dst
__device__ float g_alpha[MAXE];             // per-edge exp(logit)
__device__ float g_sum;                     // softmax denominator

// ---------------- small helpers ----------------
__device__ __forceinline__ float warpSum(float v) {
    #pragma unroll
    for (int o = 16; o > 0; o >>= 1) v += __shfl_xor_sync(0xFFFFFFFFu, v, o);
    return v;
}

// ---------------- K1: xacc[row[e]] += x[col[e]]  (fp32 gather -> fp16 atomics) ------
__global__ __launch_bounds__(256) void scatter_kernel(const int* __restrict__ ei,
                                                      const float* __restrict__ x, int E) {
    int e = (blockIdx.x * blockDim.x + threadIdx.x) >> 5;
    int lane = threadIdx.x & 31;
    if (e >= E) return;
    int r = ei[e];
    int c = ei[E + e];
    float4 v = reinterpret_cast<const float4*>(x + (size_t)c * F)[lane];
    __half2 p0 = __floats2half2_rn(v.x, v.y);
    __half2 p1 = __floats2half2_rn(v.z, v.w);
    uint32_t u0 = *reinterpret_cast<uint32_t*>(&p0);
    uint32_t u1 = *reinterpret_cast<uint32_t*>(&p1);
    __half* dst = &g_xacc[(size_t)r * F + lane * 4];
    asm volatile("red.global.add.noftz.v2.f16x2 [%0], {%1,%2};"
                 :: "l"(dst), "r"(u0), "r"(u1)
                 : "memory");
}

// ---------------- K2: acc = relu(xacc @ W + bias); s,d dots fused in epilogue -------
// 256 threads, 8 warps = 4(M) x 2(N); warp tile 32x64 = 2x4 m16n16k16 frags.
// xacc is already fp16: tile loads are straight LDG.128 -> STS (no conversion).
// SMEM: W 34816 + xh 34816 = 69632 bytes -> 2 CTAs/SM.
#define WH_LD 136
#define XH_LD 136
#define SW_HALFS   (128 * WH_LD)              // 17408
#define XH_HALFS   (128 * XH_LD)              // 17408
#define GSMEM_BYTES (SW_HALFS * 2 + XH_HALFS * 2)

__global__ __launch_bounds__(256, 2) void gemm_mma_kernel(const float* __restrict__ w,
                                                          const float* __restrict__ att,
                                                          const float* __restrict__ bias,
                                                          int numTiles) {
    extern __shared__ char smem_raw[];
    __half* sW  = reinterpret_cast<__half*>(smem_raw);
    __half* sXh = reinterpret_cast<__half*>(smem_raw + SW_HALFS * 2);
    const int tid = threadIdx.x;
    const int stride = gridDim.x;

    if (blockIdx.x == 0 && tid == 0) g_sum = 0.0f;

    // Stage W (K x N row-major) once as fp16.
    #pragma unroll
    for (int i = 0; i < 16; i++) {
        int q = tid + i * 256;       // float4 id, 4096 total
        int k = q >> 5;
        int c4 = q & 31;
        float4 v = reinterpret_cast<const float4*>(w)[q];
        __half2 p0 = __floats2half2_rn(v.x, v.y);
        __half2 p1 = __floats2half2_rn(v.z, v.w);
        uint2 u;
        u.x = *reinterpret_cast<uint32_t*>(&p0);
        u.y = *reinterpret_cast<uint32_t*>(&p1);
        *reinterpret_cast<uint2*>(&sW[k * WH_LD + c4 * 4]) = u;
    }

    const int wid = tid >> 5;
    const int lane = tid & 31;
    const int warp_m = wid & 3;          // 0..3
    const int warp_n = wid >> 2;         // 0..1
    const int n0 = warp_n * 64;

    // Per-lane epilogue constants: columns n0+2*lane, n0+2*lane+1.
    const float2 as2 = *reinterpret_cast<const float2*>(att + n0 + 2 * lane);
    const float2 ad2 = *reinterpret_cast<const float2*>(att + 128 + n0 + 2 * lane);
    const float2 b2  = *reinterpret_cast<const float2*>(bias + n0 + 2 * lane);

    for (int t = blockIdx.x; t < numTiles; t += stride) {
        __syncthreads();    // prior epilogue readers done; sXh reusable as input tile

        // Load xacc tile (fp16, coalesced LDG.128) into padded SMEM.
        const uint4* src = reinterpret_cast<const uint4*>(g_xacc + (size_t)t * 128 * F);
        #pragma unroll
        for (int i = 0; i < 8; i++) {
            int q = tid + i * 256;       // uint4 id (8 halfs), 2048 total
            int r = q >> 4;
            int c8 = q & 15;
            *reinterpret_cast<uint4*>(&sXh[r * XH_LD + c8 * 8]) = src[q];
        }
        __syncthreads();

        const __half* aBase = sXh + warp_m * 32 * XH_LD;

        wmma::fragment<wmma::accumulator, 16, 16, 16, float> c[2][4];
        #pragma unroll
        for (int mi = 0; mi < 2; mi++)
            #pragma unroll
            for (int ni = 0; ni < 4; ni++) wmma::fill_fragment(c[mi][ni], 0.0f);

        #pragma unroll
        for (int kf = 0; kf < 8; kf++) {
            const int k = kf * 16;
            wmma::fragment<wmma::matrix_a, 16, 16, 16, __half, wmma::row_major> a[2];
            wmma::fragment<wmma::matrix_b, 16, 16, 16, __half, wmma::row_major> b[4];
            #pragma unroll
            for (int mi = 0; mi < 2; mi++)
                wmma::load_matrix_sync(a[mi], aBase + mi * 16 * XH_LD + k, XH_LD);
            #pragma unroll
            for (int ni = 0; ni < 4; ni++)
                wmma::load_matrix_sync(b[ni], &sW[k * WH_LD + n0 + ni * 16], WH_LD);
            #pragma unroll
            for (int mi = 0; mi < 2; mi++)
                #pragma unroll
                for (int ni = 0; ni < 4; ni++)
                    wmma::mma_sync(c[mi][ni], a[mi], b[ni], c[mi][ni]);
        }

        __syncthreads();   // all warps done reading sXh; safe to reuse as staging

        // Epilogue: bias+relu in fp32; store fp16 acc; partial s/d dots -> red.f32.
        float* myStg = reinterpret_cast<float*>(sXh) + wid * 1024;   // 16x64 fp32
        #pragma unroll
        for (int mi = 0; mi < 2; mi++) {
            #pragma unroll
            for (int ni = 0; ni < 4; ni++)
                wmma::store_matrix_sync(myStg + ni * 16, c[mi][ni], 64, wmma::mem_row_major);
            __syncwarp();
            const size_t m0 = (size_t)t * 128 + warp_m * 32 + mi * 16;
            const float2* stg2 = reinterpret_cast<const float2*>(myStg);
            #pragma unroll 4
            for (int r = 0; r < 16; r++) {
                float2 v = stg2[r * 32 + lane];
                float vx = fmaxf(v.x + b2.x, 0.f);
                float vy = fmaxf(v.y + b2.y, 0.f);
                __half2 h2 = __floats2half2_rn(vx, vy);
                *reinterpret_cast<__half2*>(&g_acc[(m0 + r) * F + n0 + lane * 2]) = h2;
                float ps = vx * as2.x + vy * as2.y;
                float pd = vx * ad2.x + vy * ad2.y;
                ps = warpSum(ps);
                pd = warpSum(pd);
                if (lane == 0) {
                    asm volatile("red.global.add.f32 [%0], %1;" :: "l"(&g_s[m0 + r]), "f"(ps) : "memory");
                    asm volatile("red.global.add.f32 [%0], %1;" :: "l"(&g_d[m0 + r]), "f"(pd) : "memory");
                }
            }
            __syncwarp();
        }
    }
}

// Tail rows [M0, N): one CTA per row, 128 threads (one per output col).
__global__ __launch_bounds__(128) void gemm_tail_kernel(const float* __restrict__ w,
                                                        const float* __restrict__ att,
                                                        const float* __restrict__ bias,
                                                        int M0, int N) {
    __shared__ float sx[F];
    __shared__ float red_s[4], red_d[4];
    int r = M0 + blockIdx.x;
    if (r >= N) return;
    int tid = threadIdx.x;
    sx[tid] = __half2float(g_xacc[(size_t)r * F + tid]);
    __syncthreads();
    float acc = 0.f;
    #pragma unroll 8
    for (int k = 0; k < F; k++) acc = fmaf(sx[k], w[k * F + tid], acc);
    float vb = fmaxf(acc + bias[tid], 0.f);
    g_acc[(size_t)r * F + tid] = __float2half_rn(vb);
    float ps = vb * att[tid];
    float pd = vb * att[128 + tid];
    ps = warpSum(ps);
    pd = warpSum(pd);
    int lane = tid & 31, wrp = tid >> 5;
    if (lane == 0) { red_s[wrp] = ps; red_d[wrp] = pd; }
    __syncthreads();
    if (tid == 0) {
        g_s[r] = red_s[0] + red_s[1] + red_s[2] + red_s[3];
        g_d[r] = red_d[0] + red_d[1] + red_d[2] + red_d[3];
    }
}

// ---------------- K3: alpha[e]=exp(leaky_relu(s[row]+d[col])); global sum ----------
// Unstable softmax (no max subtraction): logits are small dot products, |logit| << 88,
// so exp cannot overflow; result is mathematically identical to max-shifted softmax.
__global__ __launch_bounds__(256) void alpha_exp_kernel(const int* __restrict__ ei, int E) {
    int e = blockIdx.x * blockDim.x + threadIdx.x;
    int lane = threadIdx.x & 31;
    int wid = threadIdx.x >> 5;
    float ev = 0.f;
    if (e < E) {
        int r = ei[e];
        int c = ei[E + e];
        float v = g_s[r] + g_d[c];
        v = (v > 0.f) ? v : 0.2f * v;
        ev = __expf(v);
        g_alpha[e] = ev;
    }
    __shared__ float ssum[8];
    float s = warpSum(ev);
    if (lane == 0) ssum[wid] = s;
    __syncthreads();
    if (wid == 0) {
        float t = (lane < 8) ? ssum[lane] : 0.f;
        t = warpSum(t);
        if (lane == 0) atomicAdd(&g_sum, t);
    }
}

// ---------------- K4: out[i,:] = acc[i,:] * alpha[i]/sum (acc already biased+relu'd) -
__global__ __launch_bounds__(256) void scale_kernel(float* __restrict__ out, int N) {
    size_t i = (size_t)blockIdx.x * blockDim.x + threadIdx.x;  // float4 index
    if (i >= (size_t)N * 32) return;
    int node = (int)(i >> 5);
    float sc = g_alpha[node] / g_sum;
    uint2 pk = reinterpret_cast<const uint2*>(g_acc)[i];
    float2 f0 = __half22float2(*reinterpret_cast<__half2*>(&pk.x));
    float2 f1 = __half22float2(*reinterpret_cast<__half2*>(&pk.y));
    float4 v;
    v.x = f0.x * sc;
    v.y = f0.y * sc;
    v.z = f1.x * sc;
    v.w = f1.y * sc;
    reinterpret_cast<float4*>(out)[i] = v;
}

extern "C" void kernel_launch(void* const* d_in, const int* in_sizes, int n_in,
                              void* d_out, int out_size) {
    const float* x   = (const float*)d_in[0];
    const int* ei    = (const int*)d_in[1];     // edge_index: int32
    const float* w   = (const float*)d_in[2];
    const float* att = (const float*)d_in[3];
    const float* bias= (const float*)d_in[4];
    float* out       = (float*)d_out;

    int N = in_sizes[0] / F;   // 500000
    int E = in_sizes[1] / 2;   // 500000

    static void *xacc_ptr = nullptr, *s_ptr = nullptr, *d_ptr = nullptr;
    if (!xacc_ptr) {
        cudaFuncSetAttribute(gemm_mma_kernel, cudaFuncAttributeMaxDynamicSharedMemorySize, GSMEM_BYTES);
        cudaGetSymbolAddress(&xacc_ptr, g_xacc);
        cudaGetSymbolAddress(&s_ptr, g_s);
        cudaGetSymbolAddress(&d_ptr, g_d);
    }

    int fullTiles = N / 128;           // 3906
    int M0 = fullTiles * 128;          // 499968
    int tailRows = N - M0;             // 32
    int gemmGrid = 304;                // 2 CTAs/SM on 152 SMs
    if (gemmGrid > fullTiles) gemmGrid = fullTiles;

    cudaMemsetAsync(xacc_ptr, 0, (size_t)N * F * sizeof(__half));
    cudaMemsetAsync(s_ptr, 0, (size_t)N * sizeof(float));
    cudaMemsetAsync(d_ptr, 0, (size_t)N * sizeof(float));
    scatter_kernel<<<(E + 7) / 8, 256>>>(ei, x, E);
    gemm_mma_kernel<<<gemmGrid, 256, GSMEM_BYTES>>>(w, att, bias, fullTiles);
    if (tailRows > 0) gemm_tail_kernel<<<tailRows, 128>>>(w, att, bias, M0, N);
    alpha_exp_kernel<<<(E + 255) / 256, 256>>>(ei, E);
    scale_kernel<<<(int)(((size_t)N * 32 + 255) / 256), 256>>>(out, N);
}